// round 13
// baseline (speedup 1.0000x reference)
#include <cuda_runtime.h>
#include <cuda_bf16.h>
#include <cstdint>

#define LEAK 0.5f
typedef __nv_bfloat16 bf16;

// ---------------------------------------------------------------------------
// Global scratch (allocation-free). Channel-chunked bf16 layouts:
//   act buffers: [n][chunk=ci/16][y][x][16ci]   (hi and lo parts)
// Weights: fragment-vector layout [tap][chunk][co][j], j in [0,16):
//   tq=j/4, r=j%4 -> k_in_chunk = 2*tq + (r&1) + (r>>1)*8
// so each mma thread's (b0,b1) is one contiguous 8-byte LDG.64.
// ---------------------------------------------------------------------------
__device__ bf16  g_b1h[32 * 8 * 111 * 111 * 16]; // conv1 out hi (101 MB)
__device__ bf16  g_b1l[32 * 8 * 111 * 111 * 16]; // conv1 out lo
__device__ bf16  g_b2h[32 * 4 * 54 * 54 * 16];   // conv2 out hi (12 MB)
__device__ bf16  g_b2l[32 * 4 * 54 * 54 * 16];   // conv2 out lo
__device__ float g_buf3[32 * 32 * 26 * 26];      // conv3 out fp32 NCHW
__device__ bf16  g_w2f[9 * 8 * 64 * 16];         // w2 binarized, frag-vec layout
__device__ bf16  g_w3f[9 * 4 * 32 * 16];         // w3 binarized, frag-vec layout

// ---------------------------------------------------------------------------
// One-time weight binarization into frag-vector layout [tap][chunk][co][j]
// ---------------------------------------------------------------------------
__global__ __launch_bounds__(256)
void k_prep(const float* __restrict__ w2, const float* __restrict__ w3)
{
    int i = blockIdx.x * 256 + threadIdx.x;
    if (i < 9 * 8 * 64 * 16) {
        int j = i & 15, co = (i >> 4) & 63;
        int rest = i >> 10, ch = rest & 7, tap = rest >> 3;
        int tq = j >> 2, r = j & 3;
        int k = 2 * tq + (r & 1) + ((r >> 1) << 3);
        float v = w2[((size_t)co * 128 + ch * 16 + k) * 9 + tap];
        g_w2f[i] = __float2bfloat16((v >= 0.f) ? 1.f : -1.f);
    } else if (i < 9 * 8 * 64 * 16 + 9 * 4 * 32 * 16) {
        int jj = i - 9 * 8 * 64 * 16;
        int j = jj & 15, co = (jj >> 4) & 31;
        int rest = jj >> 9, ch = rest & 3, tap = rest >> 2;
        int tq = j >> 2, r = j & 3;
        int k = 2 * tq + (r & 1) + ((r >> 1) << 3);
        float v = w3[((size_t)co * 64 + ch * 16 + k) * 9 + tap];
        g_w3f[jj] = __float2bfloat16((v >= 0.f) ? 1.f : -1.f);
    }
}

// ---------------------------------------------------------------------------
// Stage 1: conv(1->128,3x3)+bias+leaky+maxpool2, scalar FFMA (K=9 only).
// Emits bf16 hi/lo in [n][cg=co/16][y][x][16] layout via smem transpose.
// (Verified best form — tensor-core conv1 variants lost to this twice.)
// ---------------------------------------------------------------------------
__global__ __launch_bounds__(256)
void k_conv1(const float* __restrict__ x, const float* __restrict__ w1,
             const float* __restrict__ b1)
{
    __shared__ __align__(16) float sx[34][36];
    __shared__ float sw[128][10];
    __shared__ float sb[128];
    __shared__ __align__(16) bf16 sh[256][16];
    __shared__ __align__(16) bf16 sl[256][16];

    const int n   = blockIdx.z;
    const int ph0 = blockIdx.y * 16, pw0 = blockIdx.x * 16;
    const int ih0 = 2 * ph0, iw0 = 2 * pw0;
    const int t   = threadIdx.x;

    const float* xn = x + (size_t)n * 224 * 224;
    for (int i = t; i < 34 * 34; i += 256) {
        int r = i / 34, c = i % 34;
        int ir = ih0 + r, ic = iw0 + c;
        sx[r][c] = (ir < 224 && ic < 224) ? xn[ir * 224 + ic] : 0.f;
    }
    for (int i = t; i < 128 * 9; i += 256)
        sw[i / 9][i % 9] = (w1[i] >= 0.f) ? 1.f : -1.f;
    if (t < 128) sb[t] = b1[t];
    __syncthreads();

    const int py = t >> 4, px = t & 15;

    float xw[4][4];
#pragma unroll
    for (int r = 0; r < 4; r++)
#pragma unroll
        for (int c = 0; c < 4; c++)
            xw[r][c] = sx[2 * py + r][2 * px + c];

    for (int cg = 0; cg < 8; cg++) {
#pragma unroll
        for (int j = 0; j < 16; j++) {
            const int co = cg * 16 + j;
            float w[9];
#pragma unroll
            for (int k = 0; k < 9; k++) w[k] = sw[co][k];
            float m = -3.4e38f;
#pragma unroll
            for (int dy = 0; dy < 2; dy++)
#pragma unroll
                for (int dx = 0; dx < 2; dx++) {
                    float a = 0.f;
#pragma unroll
                    for (int kh = 0; kh < 3; kh++)
#pragma unroll
                        for (int kw = 0; kw < 3; kw++)
                            a += w[kh * 3 + kw] * xw[dy + kh][dx + kw];
                    m = fmaxf(m, a);
                }
            m += sb[co];
            m = (m >= 0.f) ? m : LEAK * m;
            bf16 h = __float2bfloat16(m);
            sh[t][j] = h;
            sl[t][j] = __float2bfloat16(m - __bfloat162float(h));
        }
        __syncthreads();
        for (int u = t; u < 512; u += 256) {
            int pos = u >> 1, h4 = u & 1;
            int qy = pos >> 4, qx = pos & 15;
            int ph = ph0 + qy, pw = pw0 + qx;
            if (ph < 111 && pw < 111) {
                size_t gi = ((((size_t)n * 8 + cg) * 111 + ph) * 111 + pw) * 16 + h4 * 8;
                *(uint4*)&g_b1h[gi] = *(const uint4*)&sh[pos][h4 * 8];
                *(uint4*)&g_b1l[gi] = *(const uint4*)&sl[pos][h4 * 8];
            }
        }
        __syncthreads();
    }
}

// ---------------------------------------------------------------------------
// mma.sync m16n8k16 bf16 -> fp32 ; cp.async helpers
// ---------------------------------------------------------------------------
__device__ __forceinline__ void mma_bf16(float* d,
                                         unsigned a0, unsigned a1,
                                         unsigned a2, unsigned a3,
                                         unsigned b0, unsigned b1)
{
    asm volatile(
        "mma.sync.aligned.m16n8k16.row.col.f32.bf16.bf16.f32 "
        "{%0,%1,%2,%3}, {%4,%5,%6,%7}, {%8,%9}, {%0,%1,%2,%3};\n"
        : "+f"(d[0]), "+f"(d[1]), "+f"(d[2]), "+f"(d[3])
        : "r"(a0), "r"(a1), "r"(a2), "r"(a3), "r"(b0), "r"(b1));
}

__device__ __forceinline__ void cp16(void* dst, const void* src, bool p)
{
    unsigned d = (unsigned)__cvta_generic_to_shared(dst);
    asm volatile("cp.async.cg.shared.global [%0], [%1], 16, %2;"
                 :: "r"(d), "l"(src), "r"(p ? 16u : 0u));
}
__device__ __forceinline__ void cp_commit() {
    asm volatile("cp.async.commit_group;");
}
template<int N>
__device__ __forceinline__ void cp_wait() {
    asm volatile("cp.async.wait_group %0;" :: "n"(N));
}

// ---------------------------------------------------------------------------
// Stages 2/3, tensor cores. Implicit GEMM: block M = 128 conv positions
// (8 rows x 16 cols -> pooled 4x8), N = CO. 4 warps, ALL in M:
// warp tile M32 x N=CO. K = tap-loop x 16-ci chunks; bf16 hi+lo split.
// DOUBLE-buffered cp.async staging (34.6 KB smem -> 6 CTAs/SM, 24 warps).
// stage(ch+1) issued after the top barrier: copy(ch+1) overlaps MMA(ch),
// no write-during-read races, wait_group<0> is exact.
// B frags: one LDG.64 per n8-tile (frag-vec weight layout).
// OUTF=1: bf16 hi/lo chunk-last; OUTF=0: fp32 NCHW.
// ---------------------------------------------------------------------------
template<int CI, int CO, int HIN, int POUT, int OUTF>
__global__ __launch_bounds__(128, 6)
void k_conv_mma(const bf16* __restrict__ inh, const bf16* __restrict__ inl,
                const bf16* __restrict__ wf,  const float* __restrict__ bg,
                bf16* __restrict__ outh, bf16* __restrict__ outl,
                float* __restrict__ outf)
{
    constexpr int NCH   = CI / 16;
    constexpr int NCHO  = CO / 16;
    constexpr int NT    = CO / 8;        // n8 tiles per warp (8 or 4)
    constexpr int NTX   = (POUT + 7) / 8;
    constexpr int SD    = CO + 4;
    constexpr int SLOT  = 24;            // ci-slot stride (conflict-free)
    constexpr int POS   = 10 * 18;       // tile positions incl. halo
    constexpr int SX_E  = POS * SLOT;    // elems per (buf, part)
    constexpr int BUF_E = 2 * SX_E;      // hi + lo

    extern __shared__ __align__(16) char smem_raw[];
    bf16* sbuf = (bf16*)smem_raw;        // 2 x BUF_E

    const int n   = blockIdx.z;
    const int ty  = blockIdx.x / NTX, tx = blockIdx.x % NTX;
    const int ph0 = ty * 4, pw0 = tx * 8;
    const int ih0 = 2 * ph0, iw0 = 2 * pw0;

    const int t    = threadIdx.x;
    const int lane = t & 31, wm = t >> 5;   // 4 warps, all in M
    const int g    = lane >> 2, tig = lane & 3;

    float acc[2][NT][4];
#pragma unroll
    for (int mt = 0; mt < 2; mt++)
#pragma unroll
        for (int nt = 0; nt < NT; nt++)
#pragma unroll
            for (int j = 0; j < 4; j++) acc[mt][nt][j] = 0.f;

    int abase[2];
#pragma unroll
    for (int mt = 0; mt < 2; mt++)
        abase[mt] = (((2 * wm + mt) * 18) + g) * SLOT + 2 * tig;

    // staging issue: chunk ch -> buffer b (cp.async, zfill halo)
    auto stage = [&](int ch, int b) {
        const bf16* srch = inh + ((size_t)(n * NCH + ch) * HIN * HIN) * 16;
        const bf16* srcl = inl + ((size_t)(n * NCH + ch) * HIN * HIN) * 16;
        bf16* dh = sbuf + b * BUF_E;
        bf16* dl = dh + SX_E;
        for (int u = t; u < POS * 2; u += 128) {
            int pos = u >> 1, h4 = u & 1;
            int r = pos / 18, c = pos - r * 18;
            int ir = ih0 + r, ic = iw0 + c;
            bool p = (ir < HIN) && (ic < HIN);
            size_t gi = ((size_t)ir * HIN + ic) * 16 + h4 * 8;
            int si = pos * SLOT + h4 * 8;
            cp16(dh + si, srch + gi, p);
            cp16(dl + si, srcl + gi, p);
        }
    };

    stage(0, 0);
    cp_commit();

    for (int ch = 0; ch < NCH; ch++) {
        cp_wait<0>();        // stage(ch) complete (only group in flight)
        __syncthreads();     // all warps past MMA(ch-1); data of ch visible

        // overlap: copy chunk ch+1 into the other buffer during MMA(ch)
        if (ch + 1 < NCH) { stage(ch + 1, (ch + 1) & 1); cp_commit(); }

        const bf16* sx_hi = sbuf + (ch & 1) * BUF_E;
        const bf16* sx_lo = sx_hi + SX_E;
        const bf16* wfc   = wf + ((size_t)ch * CO) * 16;

#pragma unroll
        for (int kh = 0; kh < 3; kh++)
#pragma unroll
            for (int kw = 0; kw < 3; kw++) {
                const int tap  = kh * 3 + kw;
                const int toff = (kh * 18 + kw) * SLOT;

                // B fragments: one LDG.64 per n8 tile (frag-vec layout)
                unsigned b0[NT], b1[NT];
#pragma unroll
                for (int nt = 0; nt < NT; nt++) {
                    const bf16* wp = wfc + ((size_t)tap * NCH * CO +
                                            nt * 8 + g) * 16 + tig * 4;
                    uint2 bv = *(const uint2*)wp;
                    b0[nt] = bv.x;
                    b1[nt] = bv.y;
                }

#pragma unroll
                for (int mt = 0; mt < 2; mt++) {
                    int ai = abase[mt] + toff;
                    unsigned ah0 = *(const unsigned*)&sx_hi[ai];
                    unsigned ah2 = *(const unsigned*)&sx_hi[ai + 8];
                    unsigned ah1 = *(const unsigned*)&sx_hi[ai + 8 * SLOT];
                    unsigned ah3 = *(const unsigned*)&sx_hi[ai + 8 * SLOT + 8];
                    unsigned al0 = *(const unsigned*)&sx_lo[ai];
                    unsigned al2 = *(const unsigned*)&sx_lo[ai + 8];
                    unsigned al1 = *(const unsigned*)&sx_lo[ai + 8 * SLOT];
                    unsigned al3 = *(const unsigned*)&sx_lo[ai + 8 * SLOT + 8];
#pragma unroll
                    for (int nt = 0; nt < NT; nt++) {
                        mma_bf16(acc[mt][nt], ah0, ah1, ah2, ah3, b0[nt], b1[nt]);
                        mma_bf16(acc[mt][nt], al0, al1, al2, al3, b0[nt], b1[nt]);
                    }
                }
            }
        // no trailing barrier: next iteration's sync protects buffer reuse
    }
    __syncthreads();   // before overlaying smem with the epilogue buffer

    // ---- epilogue: fragments -> smem (overlay) ----
    float* sd = (float*)smem_raw;
#pragma unroll
    for (int mt = 0; mt < 2; mt++) {
        int m0 = wm * 32 + mt * 16 + g;
#pragma unroll
        for (int nt = 0; nt < NT; nt++) {
            int n0 = nt * 8 + 2 * tig;
            *(float2*)&sd[m0 * SD + n0] =
                make_float2(acc[mt][nt][0], acc[mt][nt][1]);
            *(float2*)&sd[(m0 + 8) * SD + n0] =
                make_float2(acc[mt][nt][2], acc[mt][nt][3]);
        }
    }
    __syncthreads();

    // ---- fused maxpool(2x2) + bias + leaky ----
    if (OUTF == 1) {
        // 32 pooled px x 4 chunks = 128 threads; 16 co per thread (NCHO==4)
        int pp = t >> 2, chunk = t & 3;
        int py = pp >> 3, px = pp & 7;
        int ph = ph0 + py, pw = pw0 + px;
        if (ph < POUT && pw < POUT) {
            int mA = (2 * py) * 16 + 2 * px;
            bf16 oh[16], ol[16];
#pragma unroll
            for (int j = 0; j < 16; j++) {
                int co = chunk * 16 + j;
                float v0 = sd[mA * SD + co];
                float v1 = sd[(mA + 1) * SD + co];
                float v2 = sd[(mA + 16) * SD + co];
                float v3 = sd[(mA + 17) * SD + co];
                float m = fmaxf(fmaxf(v0, v1), fmaxf(v2, v3));
                m += __ldg(&bg[co]);
                m = (m >= 0.f) ? m : LEAK * m;
                bf16 hh = __float2bfloat16(m);
                oh[j] = hh;
                ol[j] = __float2bfloat16(m - __bfloat162float(hh));
            }
            size_t gi = ((((size_t)n * NCHO + chunk) * POUT + ph) * POUT + pw) * 16;
            *(uint4*)&outh[gi]     = *(const uint4*)&oh[0];
            *(uint4*)&outh[gi + 8] = *(const uint4*)&oh[8];
            *(uint4*)&outl[gi]     = *(const uint4*)&ol[0];
            *(uint4*)&outl[gi + 8] = *(const uint4*)&ol[8];
        }
    } else {
        // fp32 NCHW output (feeds scalar conv4): 32 px x 4 co-groups of 8
        int pp = t >> 2, cq = t & 3;
        int py = pp >> 3, px = pp & 7;
        int ph = ph0 + py, pw = pw0 + px;
        if (ph < POUT && pw < POUT) {
            int mA = (2 * py) * 16 + 2 * px;
#pragma unroll
            for (int j = 0; j < 8; j++) {
                int co = cq * 8 + j;
                float v0 = sd[mA * SD + co];
                float v1 = sd[(mA + 1) * SD + co];
                float v2 = sd[(mA + 16) * SD + co];
                float v3 = sd[(mA + 17) * SD + co];
                float m = fmaxf(fmaxf(v0, v1), fmaxf(v2, v3));
                m += __ldg(&bg[co]);
                m = (m >= 0.f) ? m : LEAK * m;
                outf[(((size_t)n * CO + co) * POUT + ph) * POUT + pw] = m;
            }
        }
    }
}

// ---------------------------------------------------------------------------
// Stage 4: conv(32->8, kh=3 kw=2) + bias, no pool.
// ---------------------------------------------------------------------------
__global__ __launch_bounds__(256)
void k_conv4(const float* __restrict__ w4, const float* __restrict__ b4,
             float* __restrict__ out)
{
    __shared__ float sw[8][32][3][2];
    __shared__ float sb[8];
    const int t = threadIdx.x;
    for (int i = t; i < 8 * 32 * 6; i += 256)
        ((float*)sw)[i] = (w4[i] >= 0.f) ? 1.f : -1.f;
    if (t < 8) sb[t] = b4[t];
    __syncthreads();

    int idx = blockIdx.x * 256 + t;
    if (idx >= 32 * 8 * 24 * 25) return;
    int ow = idx % 25; int r = idx / 25;
    int oh = r % 24;   r /= 24;
    int co = r % 8;    int n = r / 8;

    const float* xn = g_buf3 + ((size_t)n * 32) * (26 * 26);
    float a = sb[co];
#pragma unroll 4
    for (int ci = 0; ci < 32; ci++) {
        const float* xr = xn + ci * 676 + oh * 26 + ow;
#pragma unroll
        for (int kh = 0; kh < 3; kh++)
#pragma unroll
            for (int kw = 0; kw < 2; kw++)
                a += sw[co][ci][kh][kw] * __ldg(&xr[kh * 26 + kw]);
    }
    out[idx] = a;
}

// ---------------------------------------------------------------------------
extern "C" void kernel_launch(void* const* d_in, const int* in_sizes, int n_in,
                              void* d_out, int out_size)
{
    (void)in_sizes; (void)n_in; (void)out_size;
    const float* x  = (const float*)d_in[0];
    const float* w1 = (const float*)d_in[1];
    const float* b1 = (const float*)d_in[2];
    const float* w2 = (const float*)d_in[3];
    const float* b2 = (const float*)d_in[4];
    const float* w3 = (const float*)d_in[5];
    const float* b3 = (const float*)d_in[6];
    const float* w4 = (const float*)d_in[7];
    const float* b4 = (const float*)d_in[8];
    float* out = (float*)d_out;

    bf16 *b1h, *b1l, *b2h, *b2l, *w2f, *w3f;
    float* buf3;
    cudaGetSymbolAddress((void**)&b1h, g_b1h);
    cudaGetSymbolAddress((void**)&b1l, g_b1l);
    cudaGetSymbolAddress((void**)&b2h, g_b2h);
    cudaGetSymbolAddress((void**)&b2l, g_b2l);
    cudaGetSymbolAddress((void**)&w2f, g_w2f);
    cudaGetSymbolAddress((void**)&w3f, g_w3f);
    cudaGetSymbolAddress((void**)&buf3, g_buf3);

    // smem: 2 staging buffers (2*2*4320*2B = 34560) >= epilogue needs
    //   conv2 epilogue: 128*(64+4)*4 = 34816 > 34560 -> use 34816
    const int smem2 = 128 * (64 + 4) * 4;          // 34816
    const int smem3 = 2 * 2 * (10 * 18 * 24) * 2;  // 34560 (> epi 18432)

    k_prep<<<dim3(360), 256>>>(w2, w3);

    k_conv1<<<dim3(7, 7, 32), 256>>>(x, w1, b1);

    // conv2: POUT=54 -> y tiles of 4 (14), x tiles of 8 (7)
    k_conv_mma<128, 64, 111, 54, 1><<<dim3(14 * 7, 1, 32), 128, smem2>>>(
        b1h, b1l, w2f, b2, b2h, b2l, nullptr);

    // conv3: POUT=26 -> y tiles 7, x tiles 4
    k_conv_mma<64, 32, 54, 26, 0><<<dim3(7 * 4, 1, 32), 128, smem3>>>(
        b2h, b2l, w3f, b3, nullptr, nullptr, buf3);

    k_conv4<<<dim3((32 * 8 * 24 * 25 + 255) / 256), 256>>>(w4, b4, out);
}

// round 14
// speedup vs baseline: 2.1824x; 2.1824x over previous
#include <cuda_runtime.h>
#include <cuda_bf16.h>
#include <cstdint>

#define LEAK 0.5f
typedef __nv_bfloat16 bf16;

// ---------------------------------------------------------------------------
// Global scratch (allocation-free). Channel-chunked bf16 layouts:
//   act buffers: [n][chunk=ci/16][y][x][16ci]   (hi and lo parts)
// Weights: fragment-vector layout [tap][chunk][co][j], j in [0,16):
//   tq=j/4, r=j%4 -> k_in_chunk = 2*tq + (r&1) + (r>>1)*8
// so each mma thread's (b0,b1) is one contiguous 8-byte LDG.64.
// ---------------------------------------------------------------------------
__device__ bf16  g_b1h[32 * 8 * 111 * 111 * 16]; // conv1 out hi (101 MB)
__device__ bf16  g_b1l[32 * 8 * 111 * 111 * 16]; // conv1 out lo
__device__ bf16  g_b2h[32 * 4 * 54 * 54 * 16];   // conv2 out hi (12 MB)
__device__ bf16  g_b2l[32 * 4 * 54 * 54 * 16];   // conv2 out lo
__device__ float g_buf3[32 * 32 * 26 * 26];      // conv3 out fp32 NCHW
__device__ bf16  g_w2f[9 * 8 * 64 * 16];         // w2 binarized, frag-vec layout
__device__ bf16  g_w3f[9 * 4 * 32 * 16];         // w3 binarized, frag-vec layout

// ---------------------------------------------------------------------------
// One-time weight binarization into frag-vector layout [tap][chunk][co][j]
// ---------------------------------------------------------------------------
__global__ __launch_bounds__(256)
void k_prep(const float* __restrict__ w2, const float* __restrict__ w3)
{
    int i = blockIdx.x * 256 + threadIdx.x;
    if (i < 9 * 8 * 64 * 16) {
        int j = i & 15, co = (i >> 4) & 63;
        int rest = i >> 10, ch = rest & 7, tap = rest >> 3;
        int tq = j >> 2, r = j & 3;
        int k = 2 * tq + (r & 1) + ((r >> 1) << 3);
        float v = w2[((size_t)co * 128 + ch * 16 + k) * 9 + tap];
        g_w2f[i] = __float2bfloat16((v >= 0.f) ? 1.f : -1.f);
    } else if (i < 9 * 8 * 64 * 16 + 9 * 4 * 32 * 16) {
        int jj = i - 9 * 8 * 64 * 16;
        int j = jj & 15, co = (jj >> 4) & 31;
        int rest = jj >> 9, ch = rest & 3, tap = rest >> 2;
        int tq = j >> 2, r = j & 3;
        int k = 2 * tq + (r & 1) + ((r >> 1) << 3);
        float v = w3[((size_t)co * 64 + ch * 16 + k) * 9 + tap];
        g_w3f[jj] = __float2bfloat16((v >= 0.f) ? 1.f : -1.f);
    }
}

// ---------------------------------------------------------------------------
// Stage 1: conv(1->128,3x3)+bias+leaky+maxpool2, scalar FFMA (K=9 only).
// Emits bf16 hi/lo in [n][cg=co/16][y][x][16] layout via smem transpose.
// (Verified best form — tensor-core conv1 variants lost to this twice.)
// ---------------------------------------------------------------------------
__global__ __launch_bounds__(256)
void k_conv1(const float* __restrict__ x, const float* __restrict__ w1,
             const float* __restrict__ b1)
{
    __shared__ __align__(16) float sx[34][36];
    __shared__ float sw[128][10];
    __shared__ float sb[128];
    __shared__ __align__(16) bf16 sh[256][16];
    __shared__ __align__(16) bf16 sl[256][16];

    const int n   = blockIdx.z;
    const int ph0 = blockIdx.y * 16, pw0 = blockIdx.x * 16;
    const int ih0 = 2 * ph0, iw0 = 2 * pw0;
    const int t   = threadIdx.x;

    const float* xn = x + (size_t)n * 224 * 224;
    for (int i = t; i < 34 * 34; i += 256) {
        int r = i / 34, c = i % 34;
        int ir = ih0 + r, ic = iw0 + c;
        sx[r][c] = (ir < 224 && ic < 224) ? xn[ir * 224 + ic] : 0.f;
    }
    for (int i = t; i < 128 * 9; i += 256)
        sw[i / 9][i % 9] = (w1[i] >= 0.f) ? 1.f : -1.f;
    if (t < 128) sb[t] = b1[t];
    __syncthreads();

    const int py = t >> 4, px = t & 15;

    float xw[4][4];
#pragma unroll
    for (int r = 0; r < 4; r++)
#pragma unroll
        for (int c = 0; c < 4; c++)
            xw[r][c] = sx[2 * py + r][2 * px + c];

    for (int cg = 0; cg < 8; cg++) {
#pragma unroll
        for (int j = 0; j < 16; j++) {
            const int co = cg * 16 + j;
            float w[9];
#pragma unroll
            for (int k = 0; k < 9; k++) w[k] = sw[co][k];
            float m = -3.4e38f;
#pragma unroll
            for (int dy = 0; dy < 2; dy++)
#pragma unroll
                for (int dx = 0; dx < 2; dx++) {
                    float a = 0.f;
#pragma unroll
                    for (int kh = 0; kh < 3; kh++)
#pragma unroll
                        for (int kw = 0; kw < 3; kw++)
                            a += w[kh * 3 + kw] * xw[dy + kh][dx + kw];
                    m = fmaxf(m, a);
                }
            m += sb[co];
            m = (m >= 0.f) ? m : LEAK * m;
            bf16 h = __float2bfloat16(m);
            sh[t][j] = h;
            sl[t][j] = __float2bfloat16(m - __bfloat162float(h));
        }
        __syncthreads();
        for (int u = t; u < 512; u += 256) {
            int pos = u >> 1, h4 = u & 1;
            int qy = pos >> 4, qx = pos & 15;
            int ph = ph0 + qy, pw = pw0 + qx;
            if (ph < 111 && pw < 111) {
                size_t gi = ((((size_t)n * 8 + cg) * 111 + ph) * 111 + pw) * 16 + h4 * 8;
                *(uint4*)&g_b1h[gi] = *(const uint4*)&sh[pos][h4 * 8];
                *(uint4*)&g_b1l[gi] = *(const uint4*)&sl[pos][h4 * 8];
            }
        }
        __syncthreads();
    }
}

// ---------------------------------------------------------------------------
// mma.sync m16n8k16 bf16 -> fp32 ; cp.async helpers
// ---------------------------------------------------------------------------
__device__ __forceinline__ void mma_bf16(float* d,
                                         unsigned a0, unsigned a1,
                                         unsigned a2, unsigned a3,
                                         unsigned b0, unsigned b1)
{
    asm volatile(
        "mma.sync.aligned.m16n8k16.row.col.f32.bf16.bf16.f32 "
        "{%0,%1,%2,%3}, {%4,%5,%6,%7}, {%8,%9}, {%0,%1,%2,%3};\n"
        : "+f"(d[0]), "+f"(d[1]), "+f"(d[2]), "+f"(d[3])
        : "r"(a0), "r"(a1), "r"(a2), "r"(a3), "r"(b0), "r"(b1));
}

__device__ __forceinline__ void cp16(void* dst, const void* src, bool p)
{
    unsigned d = (unsigned)__cvta_generic_to_shared(dst);
    asm volatile("cp.async.cg.shared.global [%0], [%1], 16, %2;"
                 :: "r"(d), "l"(src), "r"(p ? 16u : 0u));
}
__device__ __forceinline__ void cp_commit() {
    asm volatile("cp.async.commit_group;");
}
template<int N>
__device__ __forceinline__ void cp_wait() {
    asm volatile("cp.async.wait_group %0;" :: "n"(N));
}

// ---------------------------------------------------------------------------
// Stages 2/3, tensor cores. Implicit GEMM: block M = 128 conv positions
// (8 rows x 16 cols -> pooled 4x8), N = CO. 4 warps, ALL in M:
// warp tile M32 x N=CO. K = tap-loop x 16-ci chunks; bf16 hi+lo split.
// Double-buffered cp.async staging; stage(ch+1) issued after the top
// barrier so copy(ch+1) overlaps MMA(ch) race-free; wait_group<0> exact.
// B frags: one LDG.64 per n8-tile (frag-vec weight layout).
// MINB: min-blocks occupancy clause. conv3 (NT=4, ~80 regs) takes MINB=6
// (verified 6 CTAs/SM no-spill); conv2 (NT=8, ~124 regs) takes MINB=1 —
// a reg cap there causes catastrophic spill (R13 evidence).
// OUTF=1: bf16 hi/lo chunk-last; OUTF=0: fp32 NCHW.
// ---------------------------------------------------------------------------
template<int CI, int CO, int HIN, int POUT, int OUTF, int MINB>
__global__ __launch_bounds__(128, MINB)
void k_conv_mma(const bf16* __restrict__ inh, const bf16* __restrict__ inl,
                const bf16* __restrict__ wf,  const float* __restrict__ bg,
                bf16* __restrict__ outh, bf16* __restrict__ outl,
                float* __restrict__ outf)
{
    constexpr int NCH   = CI / 16;
    constexpr int NCHO  = CO / 16;
    constexpr int NT    = CO / 8;        // n8 tiles per warp (8 or 4)
    constexpr int NTX   = (POUT + 7) / 8;
    constexpr int SD    = CO + 4;
    constexpr int SLOT  = 24;            // ci-slot stride (conflict-free)
    constexpr int POS   = 10 * 18;       // tile positions incl. halo
    constexpr int SX_E  = POS * SLOT;    // elems per (buf, part)
    constexpr int BUF_E = 2 * SX_E;      // hi + lo

    extern __shared__ __align__(16) char smem_raw[];
    bf16* sbuf = (bf16*)smem_raw;        // 2 x BUF_E

    const int n   = blockIdx.z;
    const int ty  = blockIdx.x / NTX, tx = blockIdx.x % NTX;
    const int ph0 = ty * 4, pw0 = tx * 8;
    const int ih0 = 2 * ph0, iw0 = 2 * pw0;

    const int t    = threadIdx.x;
    const int lane = t & 31, wm = t >> 5;   // 4 warps, all in M
    const int g    = lane >> 2, tig = lane & 3;

    float acc[2][NT][4];
#pragma unroll
    for (int mt = 0; mt < 2; mt++)
#pragma unroll
        for (int nt = 0; nt < NT; nt++)
#pragma unroll
            for (int j = 0; j < 4; j++) acc[mt][nt][j] = 0.f;

    int abase[2];
#pragma unroll
    for (int mt = 0; mt < 2; mt++)
        abase[mt] = (((2 * wm + mt) * 18) + g) * SLOT + 2 * tig;

    // staging issue: chunk ch -> buffer b (cp.async, zfill halo)
    auto stage = [&](int ch, int b) {
        const bf16* srch = inh + ((size_t)(n * NCH + ch) * HIN * HIN) * 16;
        const bf16* srcl = inl + ((size_t)(n * NCH + ch) * HIN * HIN) * 16;
        bf16* dh = sbuf + b * BUF_E;
        bf16* dl = dh + SX_E;
        for (int u = t; u < POS * 2; u += 128) {
            int pos = u >> 1, h4 = u & 1;
            int r = pos / 18, c = pos - r * 18;
            int ir = ih0 + r, ic = iw0 + c;
            bool p = (ir < HIN) && (ic < HIN);
            size_t gi = ((size_t)ir * HIN + ic) * 16 + h4 * 8;
            int si = pos * SLOT + h4 * 8;
            cp16(dh + si, srch + gi, p);
            cp16(dl + si, srcl + gi, p);
        }
    };

    stage(0, 0);
    cp_commit();

    for (int ch = 0; ch < NCH; ch++) {
        cp_wait<0>();        // stage(ch) complete (only group in flight)
        __syncthreads();     // all warps past MMA(ch-1); data of ch visible

        // overlap: copy chunk ch+1 into the other buffer during MMA(ch)
        if (ch + 1 < NCH) { stage(ch + 1, (ch + 1) & 1); cp_commit(); }

        const bf16* sx_hi = sbuf + (ch & 1) * BUF_E;
        const bf16* sx_lo = sx_hi + SX_E;
        const bf16* wfc   = wf + ((size_t)ch * CO) * 16;

#pragma unroll
        for (int kh = 0; kh < 3; kh++)
#pragma unroll
            for (int kw = 0; kw < 3; kw++) {
                const int tap  = kh * 3 + kw;
                const int toff = (kh * 18 + kw) * SLOT;

                // B fragments: one LDG.64 per n8 tile (frag-vec layout)
                unsigned b0[NT], b1[NT];
#pragma unroll
                for (int nt = 0; nt < NT; nt++) {
                    const bf16* wp = wfc + ((size_t)tap * NCH * CO +
                                            nt * 8 + g) * 16 + tig * 4;
                    uint2 bv = *(const uint2*)wp;
                    b0[nt] = bv.x;
                    b1[nt] = bv.y;
                }

#pragma unroll
                for (int mt = 0; mt < 2; mt++) {
                    int ai = abase[mt] + toff;
                    unsigned ah0 = *(const unsigned*)&sx_hi[ai];
                    unsigned ah2 = *(const unsigned*)&sx_hi[ai + 8];
                    unsigned ah1 = *(const unsigned*)&sx_hi[ai + 8 * SLOT];
                    unsigned ah3 = *(const unsigned*)&sx_hi[ai + 8 * SLOT + 8];
                    unsigned al0 = *(const unsigned*)&sx_lo[ai];
                    unsigned al2 = *(const unsigned*)&sx_lo[ai + 8];
                    unsigned al1 = *(const unsigned*)&sx_lo[ai + 8 * SLOT];
                    unsigned al3 = *(const unsigned*)&sx_lo[ai + 8 * SLOT + 8];
#pragma unroll
                    for (int nt = 0; nt < NT; nt++) {
                        mma_bf16(acc[mt][nt], ah0, ah1, ah2, ah3, b0[nt], b1[nt]);
                        mma_bf16(acc[mt][nt], al0, al1, al2, al3, b0[nt], b1[nt]);
                    }
                }
            }
        // no trailing barrier: next iteration's sync protects buffer reuse
    }
    __syncthreads();   // before overlaying smem with the epilogue buffer

    // ---- epilogue: fragments -> smem (overlay) ----
    float* sd = (float*)smem_raw;
#pragma unroll
    for (int mt = 0; mt < 2; mt++) {
        int m0 = wm * 32 + mt * 16 + g;
#pragma unroll
        for (int nt = 0; nt < NT; nt++) {
            int n0 = nt * 8 + 2 * tig;
            *(float2*)&sd[m0 * SD + n0] =
                make_float2(acc[mt][nt][0], acc[mt][nt][1]);
            *(float2*)&sd[(m0 + 8) * SD + n0] =
                make_float2(acc[mt][nt][2], acc[mt][nt][3]);
        }
    }
    __syncthreads();

    // ---- fused maxpool(2x2) + bias + leaky ----
    if (OUTF == 1) {
        // 32 pooled px x 4 chunks = 128 threads; 16 co per thread (NCHO==4)
        int pp = t >> 2, chunk = t & 3;
        int py = pp >> 3, px = pp & 7;
        int ph = ph0 + py, pw = pw0 + px;
        if (ph < POUT && pw < POUT) {
            int mA = (2 * py) * 16 + 2 * px;
            bf16 oh[16], ol[16];
#pragma unroll
            for (int j = 0; j < 16; j++) {
                int co = chunk * 16 + j;
                float v0 = sd[mA * SD + co];
                float v1 = sd[(mA + 1) * SD + co];
                float v2 = sd[(mA + 16) * SD + co];
                float v3 = sd[(mA + 17) * SD + co];
                float m = fmaxf(fmaxf(v0, v1), fmaxf(v2, v3));
                m += __ldg(&bg[co]);
                m = (m >= 0.f) ? m : LEAK * m;
                bf16 hh = __float2bfloat16(m);
                oh[j] = hh;
                ol[j] = __float2bfloat16(m - __bfloat162float(hh));
            }
            size_t gi = ((((size_t)n * NCHO + chunk) * POUT + ph) * POUT + pw) * 16;
            *(uint4*)&outh[gi]     = *(const uint4*)&oh[0];
            *(uint4*)&outh[gi + 8] = *(const uint4*)&oh[8];
            *(uint4*)&outl[gi]     = *(const uint4*)&ol[0];
            *(uint4*)&outl[gi + 8] = *(const uint4*)&ol[8];
        }
    } else {
        // fp32 NCHW output (feeds scalar conv4): 32 px x 4 co-groups of 8
        int pp = t >> 2, cq = t & 3;
        int py = pp >> 3, px = pp & 7;
        int ph = ph0 + py, pw = pw0 + px;
        if (ph < POUT && pw < POUT) {
            int mA = (2 * py) * 16 + 2 * px;
#pragma unroll
            for (int j = 0; j < 8; j++) {
                int co = cq * 8 + j;
                float v0 = sd[mA * SD + co];
                float v1 = sd[(mA + 1) * SD + co];
                float v2 = sd[(mA + 16) * SD + co];
                float v3 = sd[(mA + 17) * SD + co];
                float m = fmaxf(fmaxf(v0, v1), fmaxf(v2, v3));
                m += __ldg(&bg[co]);
                m = (m >= 0.f) ? m : LEAK * m;
                outf[(((size_t)n * CO + co) * POUT + ph) * POUT + pw] = m;
            }
        }
    }
}

// ---------------------------------------------------------------------------
// Stage 4: conv(32->8, kh=3 kw=2) + bias, no pool.
// ---------------------------------------------------------------------------
__global__ __launch_bounds__(256)
void k_conv4(const float* __restrict__ w4, const float* __restrict__ b4,
             float* __restrict__ out)
{
    __shared__ float sw[8][32][3][2];
    __shared__ float sb[8];
    const int t = threadIdx.x;
    for (int i = t; i < 8 * 32 * 6; i += 256)
        ((float*)sw)[i] = (w4[i] >= 0.f) ? 1.f : -1.f;
    if (t < 8) sb[t] = b4[t];
    __syncthreads();

    int idx = blockIdx.x * 256 + t;
    if (idx >= 32 * 8 * 24 * 25) return;
    int ow = idx % 25; int r = idx / 25;
    int oh = r % 24;   r /= 24;
    int co = r % 8;    int n = r / 8;

    const float* xn = g_buf3 + ((size_t)n * 32) * (26 * 26);
    float a = sb[co];
#pragma unroll 4
    for (int ci = 0; ci < 32; ci++) {
        const float* xr = xn + ci * 676 + oh * 26 + ow;
#pragma unroll
        for (int kh = 0; kh < 3; kh++)
#pragma unroll
            for (int kw = 0; kw < 2; kw++)
                a += sw[co][ci][kh][kw] * __ldg(&xr[kh * 26 + kw]);
    }
    out[idx] = a;
}

// ---------------------------------------------------------------------------
extern "C" void kernel_launch(void* const* d_in, const int* in_sizes, int n_in,
                              void* d_out, int out_size)
{
    (void)in_sizes; (void)n_in; (void)out_size;
    const float* x  = (const float*)d_in[0];
    const float* w1 = (const float*)d_in[1];
    const float* b1 = (const float*)d_in[2];
    const float* w2 = (const float*)d_in[3];
    const float* b2 = (const float*)d_in[4];
    const float* w3 = (const float*)d_in[5];
    const float* b3 = (const float*)d_in[6];
    const float* w4 = (const float*)d_in[7];
    const float* b4 = (const float*)d_in[8];
    float* out = (float*)d_out;

    bf16 *b1h, *b1l, *b2h, *b2l, *w2f, *w3f;
    float* buf3;
    cudaGetSymbolAddress((void**)&b1h, g_b1h);
    cudaGetSymbolAddress((void**)&b1l, g_b1l);
    cudaGetSymbolAddress((void**)&b2h, g_b2h);
    cudaGetSymbolAddress((void**)&b2l, g_b2l);
    cudaGetSymbolAddress((void**)&w2f, g_w2f);
    cudaGetSymbolAddress((void**)&w3f, g_w3f);
    cudaGetSymbolAddress((void**)&buf3, g_buf3);

    // smem: 2 staging buffers (2*2*4320*2B = 34560) >= epilogue needs
    //   conv2 epilogue: 128*(64+4)*4 = 34816 > 34560 -> use 34816
    const int smem2 = 128 * (64 + 4) * 4;          // 34816
    const int smem3 = 2 * 2 * (10 * 18 * 24) * 2;  // 34560 (> epi 18432)

    k_prep<<<dim3(360), 256>>>(w2, w3);

    k_conv1<<<dim3(7, 7, 32), 256>>>(x, w1, b1);

    // conv2: MINB=1 (no reg cap — NT=8 needs ~124 regs; capping spills)
    k_conv_mma<128, 64, 111, 54, 1, 1><<<dim3(14 * 7, 1, 32), 128, smem2>>>(
        b1h, b1l, w2f, b2, b2h, b2l, nullptr);

    // conv3: MINB=6 (verified: 80 regs, 6 CTAs/SM, 29.8us in R13)
    k_conv_mma<64, 32, 54, 26, 0, 6><<<dim3(7 * 4, 1, 32), 128, smem3>>>(
        b2h, b2l, w3f, b3, nullptr, nullptr, buf3);

    k_conv4<<<dim3((32 * 8 * 24 * 25 + 255) / 256), 256>>>(w4, b4, out);
}

// round 15
// speedup vs baseline: 2.2286x; 1.0212x over previous
#include <cuda_runtime.h>
#include <cuda_bf16.h>
#include <cstdint>

#define LEAK 0.5f
typedef __nv_bfloat16 bf16;

// ---------------------------------------------------------------------------
// Global scratch (allocation-free). Channel-chunked bf16 layouts:
//   act buffers: [n][chunk=ci/16][y][x][16ci]   (hi and lo parts)
// Weights: fragment-vector layout [tap][chunk][co][j], j in [0,16):
//   tq=j/4, r=j%4 -> k_in_chunk = 2*tq + (r&1) + (r>>1)*8
// so each mma thread's (b0,b1) is one contiguous 8-byte LDG.64.
// ---------------------------------------------------------------------------
__device__ bf16  g_b1h[32 * 8 * 111 * 111 * 16]; // conv1 out hi (101 MB)
__device__ bf16  g_b1l[32 * 8 * 111 * 111 * 16]; // conv1 out lo
__device__ bf16  g_b2h[32 * 4 * 54 * 54 * 16];   // conv2 out hi (12 MB)
__device__ bf16  g_b2l[32 * 4 * 54 * 54 * 16];   // conv2 out lo
__device__ float g_buf3[32 * 32 * 26 * 26];      // conv3 out fp32 NCHW
__device__ bf16  g_w2f[9 * 8 * 64 * 16];         // w2 binarized, frag-vec layout
__device__ bf16  g_w3f[9 * 4 * 32 * 16];         // w3 binarized, frag-vec layout

// ---------------------------------------------------------------------------
// One-time weight binarization into frag-vector layout [tap][chunk][co][j]
// ---------------------------------------------------------------------------
__global__ __launch_bounds__(256)
void k_prep(const float* __restrict__ w2, const float* __restrict__ w3)
{
    int i = blockIdx.x * 256 + threadIdx.x;
    if (i < 9 * 8 * 64 * 16) {
        int j = i & 15, co = (i >> 4) & 63;
        int rest = i >> 10, ch = rest & 7, tap = rest >> 3;
        int tq = j >> 2, r = j & 3;
        int k = 2 * tq + (r & 1) + ((r >> 1) << 3);
        float v = w2[((size_t)co * 128 + ch * 16 + k) * 9 + tap];
        g_w2f[i] = __float2bfloat16((v >= 0.f) ? 1.f : -1.f);
    } else if (i < 9 * 8 * 64 * 16 + 9 * 4 * 32 * 16) {
        int jj = i - 9 * 8 * 64 * 16;
        int j = jj & 15, co = (jj >> 4) & 31;
        int rest = jj >> 9, ch = rest & 3, tap = rest >> 2;
        int tq = j >> 2, r = j & 3;
        int k = 2 * tq + (r & 1) + ((r >> 1) << 3);
        float v = w3[((size_t)co * 64 + ch * 16 + k) * 9 + tap];
        g_w3f[jj] = __float2bfloat16((v >= 0.f) ? 1.f : -1.f);
    }
}

// ---------------------------------------------------------------------------
// Stage 1: conv(1->128,3x3)+bias+leaky+maxpool2, scalar FFMA (K=9 only).
// Emits bf16 hi/lo in [n][cg=co/16][y][x][16] layout via smem transpose.
// (Verified best form — tensor-core conv1 variants lost to this twice.)
// ---------------------------------------------------------------------------
__global__ __launch_bounds__(256)
void k_conv1(const float* __restrict__ x, const float* __restrict__ w1,
             const float* __restrict__ b1)
{
    __shared__ __align__(16) float sx[34][36];
    __shared__ float sw[128][10];
    __shared__ float sb[128];
    __shared__ __align__(16) bf16 sh[256][16];
    __shared__ __align__(16) bf16 sl[256][16];

    const int n   = blockIdx.z;
    const int ph0 = blockIdx.y * 16, pw0 = blockIdx.x * 16;
    const int ih0 = 2 * ph0, iw0 = 2 * pw0;
    const int t   = threadIdx.x;

    const float* xn = x + (size_t)n * 224 * 224;
    for (int i = t; i < 34 * 34; i += 256) {
        int r = i / 34, c = i % 34;
        int ir = ih0 + r, ic = iw0 + c;
        sx[r][c] = (ir < 224 && ic < 224) ? xn[ir * 224 + ic] : 0.f;
    }
    for (int i = t; i < 128 * 9; i += 256)
        sw[i / 9][i % 9] = (w1[i] >= 0.f) ? 1.f : -1.f;
    if (t < 128) sb[t] = b1[t];
    __syncthreads();

    const int py = t >> 4, px = t & 15;

    float xw[4][4];
#pragma unroll
    for (int r = 0; r < 4; r++)
#pragma unroll
        for (int c = 0; c < 4; c++)
            xw[r][c] = sx[2 * py + r][2 * px + c];

    for (int cg = 0; cg < 8; cg++) {
#pragma unroll
        for (int j = 0; j < 16; j++) {
            const int co = cg * 16 + j;
            float w[9];
#pragma unroll
            for (int k = 0; k < 9; k++) w[k] = sw[co][k];
            float m = -3.4e38f;
#pragma unroll
            for (int dy = 0; dy < 2; dy++)
#pragma unroll
                for (int dx = 0; dx < 2; dx++) {
                    float a = 0.f;
#pragma unroll
                    for (int kh = 0; kh < 3; kh++)
#pragma unroll
                        for (int kw = 0; kw < 3; kw++)
                            a += w[kh * 3 + kw] * xw[dy + kh][dx + kw];
                    m = fmaxf(m, a);
                }
            m += sb[co];
            m = (m >= 0.f) ? m : LEAK * m;
            bf16 h = __float2bfloat16(m);
            sh[t][j] = h;
            sl[t][j] = __float2bfloat16(m - __bfloat162float(h));
        }
        __syncthreads();
        for (int u = t; u < 512; u += 256) {
            int pos = u >> 1, h4 = u & 1;
            int qy = pos >> 4, qx = pos & 15;
            int ph = ph0 + qy, pw = pw0 + qx;
            if (ph < 111 && pw < 111) {
                size_t gi = ((((size_t)n * 8 + cg) * 111 + ph) * 111 + pw) * 16 + h4 * 8;
                *(uint4*)&g_b1h[gi] = *(const uint4*)&sh[pos][h4 * 8];
                *(uint4*)&g_b1l[gi] = *(const uint4*)&sl[pos][h4 * 8];
            }
        }
        __syncthreads();
    }
}

// ---------------------------------------------------------------------------
// mma.sync m16n8k16 bf16 -> fp32 ; cp.async helpers
// ---------------------------------------------------------------------------
__device__ __forceinline__ void mma_bf16(float* d,
                                         unsigned a0, unsigned a1,
                                         unsigned a2, unsigned a3,
                                         unsigned b0, unsigned b1)
{
    asm volatile(
        "mma.sync.aligned.m16n8k16.row.col.f32.bf16.bf16.f32 "
        "{%0,%1,%2,%3}, {%4,%5,%6,%7}, {%8,%9}, {%0,%1,%2,%3};\n"
        : "+f"(d[0]), "+f"(d[1]), "+f"(d[2]), "+f"(d[3])
        : "r"(a0), "r"(a1), "r"(a2), "r"(a3), "r"(b0), "r"(b1));
}

__device__ __forceinline__ void cp16(void* dst, const void* src, bool p)
{
    unsigned d = (unsigned)__cvta_generic_to_shared(dst);
    asm volatile("cp.async.cg.shared.global [%0], [%1], 16, %2;"
                 :: "r"(d), "l"(src), "r"(p ? 16u : 0u));
}
__device__ __forceinline__ void cp_commit() {
    asm volatile("cp.async.commit_group;");
}
template<int N>
__device__ __forceinline__ void cp_wait() {
    asm volatile("cp.async.wait_group %0;" :: "n"(N));
}

// ---------------------------------------------------------------------------
// Stages 2/3, tensor cores. Implicit GEMM: block M = 128 conv positions
// (8 rows x 16 cols -> pooled 4x8), N = CO. 4 warps, ALL in M:
// warp tile M32 x N=CO. K = tap-loop x 16-ci chunks; bf16 hi+lo split.
// B frags: one LDG.64 per n8-tile (frag-vec weight layout).
//
// NBUF=3 (conv2, R10-verified): triple-buffered, depth-2 prefetch
//   (stage 0/1 pre-issued, wait<1>, stage(ch+2) after barrier).
// NBUF=2 (conv3, R13/R14-verified): double-buffered, wait<0>,
//   stage(ch+1) after barrier; pairs with MINB=6 (80 regs, 6 CTAs/SM).
// MINB: conv2 -> 1 (reg cap would spill: ~124 regs needed, R13 evidence);
//       conv3 -> 6.
// OUTF=1: bf16 hi/lo chunk-last; OUTF=0: fp32 NCHW.
// ---------------------------------------------------------------------------
template<int CI, int CO, int HIN, int POUT, int OUTF, int MINB, int NBUF>
__global__ __launch_bounds__(128, MINB)
void k_conv_mma(const bf16* __restrict__ inh, const bf16* __restrict__ inl,
                const bf16* __restrict__ wf,  const float* __restrict__ bg,
                bf16* __restrict__ outh, bf16* __restrict__ outl,
                float* __restrict__ outf)
{
    constexpr int NCH   = CI / 16;
    constexpr int NCHO  = CO / 16;
    constexpr int NT    = CO / 8;        // n8 tiles per warp (8 or 4)
    constexpr int NTX   = (POUT + 7) / 8;
    constexpr int SD    = CO + 4;
    constexpr int SLOT  = 24;            // ci-slot stride (conflict-free)
    constexpr int POS   = 10 * 18;       // tile positions incl. halo
    constexpr int SX_E  = POS * SLOT;    // elems per (buf, part)
    constexpr int BUF_E = 2 * SX_E;      // hi + lo

    extern __shared__ __align__(16) char smem_raw[];
    bf16* sbuf = (bf16*)smem_raw;        // NBUF x BUF_E

    const int n   = blockIdx.z;
    const int ty  = blockIdx.x / NTX, tx = blockIdx.x % NTX;
    const int ph0 = ty * 4, pw0 = tx * 8;
    const int ih0 = 2 * ph0, iw0 = 2 * pw0;

    const int t    = threadIdx.x;
    const int lane = t & 31, wm = t >> 5;   // 4 warps, all in M
    const int g    = lane >> 2, tig = lane & 3;

    float acc[2][NT][4];
#pragma unroll
    for (int mt = 0; mt < 2; mt++)
#pragma unroll
        for (int nt = 0; nt < NT; nt++)
#pragma unroll
            for (int j = 0; j < 4; j++) acc[mt][nt][j] = 0.f;

    int abase[2];
#pragma unroll
    for (int mt = 0; mt < 2; mt++)
        abase[mt] = (((2 * wm + mt) * 18) + g) * SLOT + 2 * tig;

    // staging issue: chunk ch -> buffer b (cp.async, zfill halo)
    auto stage = [&](int ch, int b) {
        const bf16* srch = inh + ((size_t)(n * NCH + ch) * HIN * HIN) * 16;
        const bf16* srcl = inl + ((size_t)(n * NCH + ch) * HIN * HIN) * 16;
        bf16* dh = sbuf + b * BUF_E;
        bf16* dl = dh + SX_E;
        for (int u = t; u < POS * 2; u += 128) {
            int pos = u >> 1, h4 = u & 1;
            int r = pos / 18, c = pos - r * 18;
            int ir = ih0 + r, ic = iw0 + c;
            bool p = (ir < HIN) && (ic < HIN);
            size_t gi = ((size_t)ir * HIN + ic) * 16 + h4 * 8;
            int si = pos * SLOT + h4 * 8;
            cp16(dh + si, srch + gi, p);
            cp16(dl + si, srcl + gi, p);
        }
    };

    stage(0, 0);
    cp_commit();
    if (NBUF == 3 && NCH > 1) { stage(1, 1); cp_commit(); }

    for (int ch = 0; ch < NCH; ch++) {
        if (NBUF == 3) {
            // depth-2 pipeline: one younger group may stay in flight
            if (ch + 1 < NCH) cp_wait<1>(); else cp_wait<0>();
            __syncthreads();
            if (ch + 2 < NCH) { stage(ch + 2, (ch + 2) % 3); cp_commit(); }
        } else {
            cp_wait<0>();        // stage(ch) complete
            __syncthreads();
            if (ch + 1 < NCH) { stage(ch + 1, (ch + 1) & 1); cp_commit(); }
        }

        const bf16* sx_hi = sbuf + (NBUF == 3 ? (ch % 3) : (ch & 1)) * BUF_E;
        const bf16* sx_lo = sx_hi + SX_E;
        const bf16* wfc   = wf + ((size_t)ch * CO) * 16;

#pragma unroll
        for (int kh = 0; kh < 3; kh++)
#pragma unroll
            for (int kw = 0; kw < 3; kw++) {
                const int tap  = kh * 3 + kw;
                const int toff = (kh * 18 + kw) * SLOT;

                // B fragments: one LDG.64 per n8 tile (frag-vec layout)
                unsigned b0[NT], b1[NT];
#pragma unroll
                for (int nt = 0; nt < NT; nt++) {
                    const bf16* wp = wfc + ((size_t)tap * NCH * CO +
                                            nt * 8 + g) * 16 + tig * 4;
                    uint2 bv = *(const uint2*)wp;
                    b0[nt] = bv.x;
                    b1[nt] = bv.y;
                }

#pragma unroll
                for (int mt = 0; mt < 2; mt++) {
                    int ai = abase[mt] + toff;
                    unsigned ah0 = *(const unsigned*)&sx_hi[ai];
                    unsigned ah2 = *(const unsigned*)&sx_hi[ai + 8];
                    unsigned ah1 = *(const unsigned*)&sx_hi[ai + 8 * SLOT];
                    unsigned ah3 = *(const unsigned*)&sx_hi[ai + 8 * SLOT + 8];
                    unsigned al0 = *(const unsigned*)&sx_lo[ai];
                    unsigned al2 = *(const unsigned*)&sx_lo[ai + 8];
                    unsigned al1 = *(const unsigned*)&sx_lo[ai + 8 * SLOT];
                    unsigned al3 = *(const unsigned*)&sx_lo[ai + 8 * SLOT + 8];
#pragma unroll
                    for (int nt = 0; nt < NT; nt++) {
                        mma_bf16(acc[mt][nt], ah0, ah1, ah2, ah3, b0[nt], b1[nt]);
                        mma_bf16(acc[mt][nt], al0, al1, al2, al3, b0[nt], b1[nt]);
                    }
                }
            }
        // no trailing barrier: next iteration's sync protects buffer reuse
    }
    __syncthreads();   // before overlaying smem with the epilogue buffer

    // ---- epilogue: fragments -> smem (overlay) ----
    float* sd = (float*)smem_raw;
#pragma unroll
    for (int mt = 0; mt < 2; mt++) {
        int m0 = wm * 32 + mt * 16 + g;
#pragma unroll
        for (int nt = 0; nt < NT; nt++) {
            int n0 = nt * 8 + 2 * tig;
            *(float2*)&sd[m0 * SD + n0] =
                make_float2(acc[mt][nt][0], acc[mt][nt][1]);
            *(float2*)&sd[(m0 + 8) * SD + n0] =
                make_float2(acc[mt][nt][2], acc[mt][nt][3]);
        }
    }
    __syncthreads();

    // ---- fused maxpool(2x2) + bias + leaky ----
    if (OUTF == 1) {
        // 32 pooled px x 4 chunks = 128 threads; 16 co per thread (NCHO==4)
        int pp = t >> 2, chunk = t & 3;
        int py = pp >> 3, px = pp & 7;
        int ph = ph0 + py, pw = pw0 + px;
        if (ph < POUT && pw < POUT) {
            int mA = (2 * py) * 16 + 2 * px;
            bf16 oh[16], ol[16];
#pragma unroll
            for (int j = 0; j < 16; j++) {
                int co = chunk * 16 + j;
                float v0 = sd[mA * SD + co];
                float v1 = sd[(mA + 1) * SD + co];
                float v2 = sd[(mA + 16) * SD + co];
                float v3 = sd[(mA + 17) * SD + co];
                float m = fmaxf(fmaxf(v0, v1), fmaxf(v2, v3));
                m += __ldg(&bg[co]);
                m = (m >= 0.f) ? m : LEAK * m;
                bf16 hh = __float2bfloat16(m);
                oh[j] = hh;
                ol[j] = __float2bfloat16(m - __bfloat162float(hh));
            }
            size_t gi = ((((size_t)n * NCHO + chunk) * POUT + ph) * POUT + pw) * 16;
            *(uint4*)&outh[gi]     = *(const uint4*)&oh[0];
            *(uint4*)&outh[gi + 8] = *(const uint4*)&oh[8];
            *(uint4*)&outl[gi]     = *(const uint4*)&ol[0];
            *(uint4*)&outl[gi + 8] = *(const uint4*)&ol[8];
        }
    } else {
        // fp32 NCHW output (feeds scalar conv4): 32 px x 4 co-groups of 8
        int pp = t >> 2, cq = t & 3;
        int py = pp >> 3, px = pp & 7;
        int ph = ph0 + py, pw = pw0 + px;
        if (ph < POUT && pw < POUT) {
            int mA = (2 * py) * 16 + 2 * px;
#pragma unroll
            for (int j = 0; j < 8; j++) {
                int co = cq * 8 + j;
                float v0 = sd[mA * SD + co];
                float v1 = sd[(mA + 1) * SD + co];
                float v2 = sd[(mA + 16) * SD + co];
                float v3 = sd[(mA + 17) * SD + co];
                float m = fmaxf(fmaxf(v0, v1), fmaxf(v2, v3));
                m += __ldg(&bg[co]);
                m = (m >= 0.f) ? m : LEAK * m;
                outf[(((size_t)n * CO + co) * POUT + ph) * POUT + pw] = m;
            }
        }
    }
}

// ---------------------------------------------------------------------------
// Stage 4: conv(32->8, kh=3 kw=2) + bias, no pool.
// ---------------------------------------------------------------------------
__global__ __launch_bounds__(256)
void k_conv4(const float* __restrict__ w4, const float* __restrict__ b4,
             float* __restrict__ out)
{
    __shared__ float sw[8][32][3][2];
    __shared__ float sb[8];
    const int t = threadIdx.x;
    for (int i = t; i < 8 * 32 * 6; i += 256)
        ((float*)sw)[i] = (w4[i] >= 0.f) ? 1.f : -1.f;
    if (t < 8) sb[t] = b4[t];
    __syncthreads();

    int idx = blockIdx.x * 256 + t;
    if (idx >= 32 * 8 * 24 * 25) return;
    int ow = idx % 25; int r = idx / 25;
    int oh = r % 24;   r /= 24;
    int co = r % 8;    int n = r / 8;

    const float* xn = g_buf3 + ((size_t)n * 32) * (26 * 26);
    float a = sb[co];
#pragma unroll 4
    for (int ci = 0; ci < 32; ci++) {
        const float* xr = xn + ci * 676 + oh * 26 + ow;
#pragma unroll
        for (int kh = 0; kh < 3; kh++)
#pragma unroll
            for (int kw = 0; kw < 2; kw++)
                a += sw[co][ci][kh][kw] * __ldg(&xr[kh * 26 + kw]);
    }
    out[idx] = a;
}

// ---------------------------------------------------------------------------
extern "C" void kernel_launch(void* const* d_in, const int* in_sizes, int n_in,
                              void* d_out, int out_size)
{
    (void)in_sizes; (void)n_in; (void)out_size;
    const float* x  = (const float*)d_in[0];
    const float* w1 = (const float*)d_in[1];
    const float* b1 = (const float*)d_in[2];
    const float* w2 = (const float*)d_in[3];
    const float* b2 = (const float*)d_in[4];
    const float* w3 = (const float*)d_in[5];
    const float* b3 = (const float*)d_in[6];
    const float* w4 = (const float*)d_in[7];
    const float* b4 = (const float*)d_in[8];
    float* out = (float*)d_out;

    bf16 *b1h, *b1l, *b2h, *b2l, *w2f, *w3f;
    float* buf3;
    cudaGetSymbolAddress((void**)&b1h, g_b1h);
    cudaGetSymbolAddress((void**)&b1l, g_b1l);
    cudaGetSymbolAddress((void**)&b2h, g_b2h);
    cudaGetSymbolAddress((void**)&b2l, g_b2l);
    cudaGetSymbolAddress((void**)&w2f, g_w2f);
    cudaGetSymbolAddress((void**)&w3f, g_w3f);
    cudaGetSymbolAddress((void**)&buf3, g_buf3);

    // conv2 smem: 3 staging buffers (3*2*4320*2B = 51840) >= epilogue 34816
    const int smem2 = 3 * 2 * (10 * 18 * 24) * 2;  // 51840
    // conv3 smem: 2 staging buffers (2*2*4320*2B = 34560) >= epilogue 18432
    const int smem3 = 2 * 2 * (10 * 18 * 24) * 2;  // 34560
    cudaFuncSetAttribute(k_conv_mma<128, 64, 111, 54, 1, 1, 3>,
                         cudaFuncAttributeMaxDynamicSharedMemorySize, smem2);

    k_prep<<<dim3(360), 256>>>(w2, w3);

    k_conv1<<<dim3(7, 7, 32), 256>>>(x, w1, b1);

    // conv2: R10-verified config — 3 buffers, depth-2 prefetch, no reg cap
    k_conv_mma<128, 64, 111, 54, 1, 1, 3><<<dim3(14 * 7, 1, 32), 128, smem2>>>(
        b1h, b1l, w2f, b2, b2h, b2l, nullptr);

    // conv3: R13/R14-verified config — 2 buffers, MINB=6 (80 regs, 6 CTA/SM)
    k_conv_mma<64, 32, 54, 26, 0, 6, 2><<<dim3(7 * 4, 1, 32), 128, smem3>>>(
        b2h, b2l, w3f, b3, nullptr, nullptr, buf3);

    k_conv4<<<dim3((32 * 8 * 24 * 25 + 255) / 256), 256>>>(w4, b4, out);
}

// round 16
// speedup vs baseline: 2.4523x; 1.1004x over previous
#include <cuda_runtime.h>
#include <cuda_bf16.h>
#include <cstdint>

#define LEAK 0.5f
typedef __nv_bfloat16 bf16;

// ---------------------------------------------------------------------------
// Global scratch (allocation-free). Channel-chunked bf16 layouts:
//   act buffers: [n][chunk=ci/16][y][x][16ci]   (hi and lo parts)
// Weights: fragment-vector layout [tap][chunk][co][j], j in [0,16):
//   tq=j/4, r=j%4 -> k_in_chunk = 2*tq + (r&1) + (r>>1)*8
// so each mma thread's (b0,b1) is one contiguous 8-byte LDG.64.
// ---------------------------------------------------------------------------
__device__ bf16  g_b1h[32 * 8 * 111 * 111 * 16]; // conv1 out hi (101 MB)
__device__ bf16  g_b1l[32 * 8 * 111 * 111 * 16]; // conv1 out lo
__device__ bf16  g_b2h[32 * 4 * 54 * 54 * 16];   // conv2 out hi (12 MB)
__device__ bf16  g_b2l[32 * 4 * 54 * 54 * 16];   // conv2 out lo
__device__ float g_buf3[32 * 32 * 26 * 26];      // conv3 out fp32 NCHW
__device__ bf16  g_w2f[9 * 8 * 64 * 16];         // w2 binarized, frag-vec layout
__device__ bf16  g_w3f[9 * 4 * 32 * 16];         // w3 binarized, frag-vec layout

// ---------------------------------------------------------------------------
// One-time weight binarization into frag-vector layout [tap][chunk][co][j]
// ---------------------------------------------------------------------------
__global__ __launch_bounds__(256)
void k_prep(const float* __restrict__ w2, const float* __restrict__ w3)
{
    int i = blockIdx.x * 256 + threadIdx.x;
    if (i < 9 * 8 * 64 * 16) {
        int j = i & 15, co = (i >> 4) & 63;
        int rest = i >> 10, ch = rest & 7, tap = rest >> 3;
        int tq = j >> 2, r = j & 3;
        int k = 2 * tq + (r & 1) + ((r >> 1) << 3);
        float v = w2[((size_t)co * 128 + ch * 16 + k) * 9 + tap];
        g_w2f[i] = __float2bfloat16((v >= 0.f) ? 1.f : -1.f);
    } else if (i < 9 * 8 * 64 * 16 + 9 * 4 * 32 * 16) {
        int jj = i - 9 * 8 * 64 * 16;
        int j = jj & 15, co = (jj >> 4) & 31;
        int rest = jj >> 9, ch = rest & 3, tap = rest >> 2;
        int tq = j >> 2, r = j & 3;
        int k = 2 * tq + (r & 1) + ((r >> 1) << 3);
        float v = w3[((size_t)co * 64 + ch * 16 + k) * 9 + tap];
        g_w3f[jj] = __float2bfloat16((v >= 0.f) ? 1.f : -1.f);
    }
}

// ---------------------------------------------------------------------------
// Stage 1: conv(1->128,3x3)+bias+leaky+maxpool2, scalar FFMA (K=9 only).
// Emits bf16 hi/lo in [n][cg=co/16][y][x][16] layout via smem transpose.
// (Verified best form — tensor-core conv1 variants lost to this twice.)
// ---------------------------------------------------------------------------
__global__ __launch_bounds__(256)
void k_conv1(const float* __restrict__ x, const float* __restrict__ w1,
             const float* __restrict__ b1)
{
    __shared__ __align__(16) float sx[34][36];
    __shared__ float sw[128][10];
    __shared__ float sb[128];
    __shared__ __align__(16) bf16 sh[256][16];
    __shared__ __align__(16) bf16 sl[256][16];

    const int n   = blockIdx.z;
    const int ph0 = blockIdx.y * 16, pw0 = blockIdx.x * 16;
    const int ih0 = 2 * ph0, iw0 = 2 * pw0;
    const int t   = threadIdx.x;

    const float* xn = x + (size_t)n * 224 * 224;
    for (int i = t; i < 34 * 34; i += 256) {
        int r = i / 34, c = i % 34;
        int ir = ih0 + r, ic = iw0 + c;
        sx[r][c] = (ir < 224 && ic < 224) ? xn[ir * 224 + ic] : 0.f;
    }
    for (int i = t; i < 128 * 9; i += 256)
        sw[i / 9][i % 9] = (w1[i] >= 0.f) ? 1.f : -1.f;
    if (t < 128) sb[t] = b1[t];
    __syncthreads();

    const int py = t >> 4, px = t & 15;

    float xw[4][4];
#pragma unroll
    for (int r = 0; r < 4; r++)
#pragma unroll
        for (int c = 0; c < 4; c++)
            xw[r][c] = sx[2 * py + r][2 * px + c];

    for (int cg = 0; cg < 8; cg++) {
#pragma unroll
        for (int j = 0; j < 16; j++) {
            const int co = cg * 16 + j;
            float w[9];
#pragma unroll
            for (int k = 0; k < 9; k++) w[k] = sw[co][k];
            float m = -3.4e38f;
#pragma unroll
            for (int dy = 0; dy < 2; dy++)
#pragma unroll
                for (int dx = 0; dx < 2; dx++) {
                    float a = 0.f;
#pragma unroll
                    for (int kh = 0; kh < 3; kh++)
#pragma unroll
                        for (int kw = 0; kw < 3; kw++)
                            a += w[kh * 3 + kw] * xw[dy + kh][dx + kw];
                    m = fmaxf(m, a);
                }
            m += sb[co];
            m = (m >= 0.f) ? m : LEAK * m;
            bf16 h = __float2bfloat16(m);
            sh[t][j] = h;
            sl[t][j] = __float2bfloat16(m - __bfloat162float(h));
        }
        __syncthreads();
        for (int u = t; u < 512; u += 256) {
            int pos = u >> 1, h4 = u & 1;
            int qy = pos >> 4, qx = pos & 15;
            int ph = ph0 + qy, pw = pw0 + qx;
            if (ph < 111 && pw < 111) {
                size_t gi = ((((size_t)n * 8 + cg) * 111 + ph) * 111 + pw) * 16 + h4 * 8;
                *(uint4*)&g_b1h[gi] = *(const uint4*)&sh[pos][h4 * 8];
                *(uint4*)&g_b1l[gi] = *(const uint4*)&sl[pos][h4 * 8];
            }
        }
        __syncthreads();
    }
}

// ---------------------------------------------------------------------------
// mma.sync m16n8k16 bf16 -> fp32 ; cp.async helpers
// ---------------------------------------------------------------------------
__device__ __forceinline__ void mma_bf16(float* d,
                                         unsigned a0, unsigned a1,
                                         unsigned a2, unsigned a3,
                                         unsigned b0, unsigned b1)
{
    asm volatile(
        "mma.sync.aligned.m16n8k16.row.col.f32.bf16.bf16.f32 "
        "{%0,%1,%2,%3}, {%4,%5,%6,%7}, {%8,%9}, {%0,%1,%2,%3};\n"
        : "+f"(d[0]), "+f"(d[1]), "+f"(d[2]), "+f"(d[3])
        : "r"(a0), "r"(a1), "r"(a2), "r"(a3), "r"(b0), "r"(b1));
}

__device__ __forceinline__ void cp16(void* dst, const void* src, bool p)
{
    unsigned d = (unsigned)__cvta_generic_to_shared(dst);
    asm volatile("cp.async.cg.shared.global [%0], [%1], 16, %2;"
                 :: "r"(d), "l"(src), "r"(p ? 16u : 0u));
}
__device__ __forceinline__ void cp_commit() {
    asm volatile("cp.async.commit_group;");
}
template<int N>
__device__ __forceinline__ void cp_wait() {
    asm volatile("cp.async.wait_group %0;" :: "n"(N));
}

// ---------------------------------------------------------------------------
// Shared mma-conv body (stages 2/3). Implicit GEMM: block M = 128 conv
// positions (8 rows x 16 cols -> pooled 4x8), N = CO. 4 warps, all in M:
// warp tile M32 x N=CO. K = tap-loop x 16-ci chunks; bf16 hi+lo split.
// B frags: one LDG.64 per n8-tile (frag-vec weight layout).
// NBUF=3: triple-buffered, depth-2 prefetch (R10-verified for conv2).
// NBUF=2: double-buffered, wait<0> (R13/14-verified for conv3).
// OUTF=1: bf16 hi/lo chunk-last out; OUTF=0: fp32 NCHW out.
// ---------------------------------------------------------------------------
template<int CI, int CO, int HIN, int POUT, int OUTF, int NBUF>
__device__ __forceinline__
void conv_mma_body(const bf16* __restrict__ inh, const bf16* __restrict__ inl,
                   const bf16* __restrict__ wf,  const float* __restrict__ bg,
                   bf16* __restrict__ outh, bf16* __restrict__ outl,
                   float* __restrict__ outf)
{
    constexpr int NCH   = CI / 16;
    constexpr int NCHO  = CO / 16;
    constexpr int NT    = CO / 8;        // n8 tiles per warp (8 or 4)
    constexpr int NTX   = (POUT + 7) / 8;
    constexpr int SD    = CO + 4;
    constexpr int SLOT  = 24;            // ci-slot stride (conflict-free)
    constexpr int POS   = 10 * 18;       // tile positions incl. halo
    constexpr int SX_E  = POS * SLOT;    // elems per (buf, part)
    constexpr int BUF_E = 2 * SX_E;      // hi + lo

    extern __shared__ __align__(16) char smem_raw[];
    bf16* sbuf = (bf16*)smem_raw;        // NBUF x BUF_E

    const int n   = blockIdx.z;
    const int ty  = blockIdx.x / NTX, tx = blockIdx.x % NTX;
    const int ph0 = ty * 4, pw0 = tx * 8;
    const int ih0 = 2 * ph0, iw0 = 2 * pw0;

    const int t    = threadIdx.x;
    const int lane = t & 31, wm = t >> 5;   // 4 warps, all in M
    const int g    = lane >> 2, tig = lane & 3;

    float acc[2][NT][4];
#pragma unroll
    for (int mt = 0; mt < 2; mt++)
#pragma unroll
        for (int nt = 0; nt < NT; nt++)
#pragma unroll
            for (int j = 0; j < 4; j++) acc[mt][nt][j] = 0.f;

    int abase[2];
#pragma unroll
    for (int mt = 0; mt < 2; mt++)
        abase[mt] = (((2 * wm + mt) * 18) + g) * SLOT + 2 * tig;

    // staging issue: chunk ch -> buffer b (cp.async, zfill halo)
    auto stage = [&](int ch, int b) {
        const bf16* srch = inh + ((size_t)(n * NCH + ch) * HIN * HIN) * 16;
        const bf16* srcl = inl + ((size_t)(n * NCH + ch) * HIN * HIN) * 16;
        bf16* dh = sbuf + b * BUF_E;
        bf16* dl = dh + SX_E;
        for (int u = t; u < POS * 2; u += 128) {
            int pos = u >> 1, h4 = u & 1;
            int r = pos / 18, c = pos - r * 18;
            int ir = ih0 + r, ic = iw0 + c;
            bool p = (ir < HIN) && (ic < HIN);
            size_t gi = ((size_t)ir * HIN + ic) * 16 + h4 * 8;
            int si = pos * SLOT + h4 * 8;
            cp16(dh + si, srch + gi, p);
            cp16(dl + si, srcl + gi, p);
        }
    };

    stage(0, 0);
    cp_commit();
    if (NBUF == 3 && NCH > 1) { stage(1, 1); cp_commit(); }

    for (int ch = 0; ch < NCH; ch++) {
        if (NBUF == 3) {
            // depth-2 pipeline: one younger group may stay in flight
            if (ch + 1 < NCH) cp_wait<1>(); else cp_wait<0>();
            __syncthreads();
            if (ch + 2 < NCH) { stage(ch + 2, (ch + 2) % 3); cp_commit(); }
        } else {
            cp_wait<0>();        // stage(ch) complete
            __syncthreads();
            if (ch + 1 < NCH) { stage(ch + 1, (ch + 1) & 1); cp_commit(); }
        }

        const bf16* sx_hi = sbuf + (NBUF == 3 ? (ch % 3) : (ch & 1)) * BUF_E;
        const bf16* sx_lo = sx_hi + SX_E;
        const bf16* wfc   = wf + ((size_t)ch * CO) * 16;

#pragma unroll
        for (int kh = 0; kh < 3; kh++)
#pragma unroll
            for (int kw = 0; kw < 3; kw++) {
                const int tap  = kh * 3 + kw;
                const int toff = (kh * 18 + kw) * SLOT;

                // B fragments: one LDG.64 per n8 tile (frag-vec layout)
                unsigned b0[NT], b1[NT];
#pragma unroll
                for (int nt = 0; nt < NT; nt++) {
                    const bf16* wp = wfc + ((size_t)tap * NCH * CO +
                                            nt * 8 + g) * 16 + tig * 4;
                    uint2 bv = *(const uint2*)wp;
                    b0[nt] = bv.x;
                    b1[nt] = bv.y;
                }

#pragma unroll
                for (int mt = 0; mt < 2; mt++) {
                    int ai = abase[mt] + toff;
                    unsigned ah0 = *(const unsigned*)&sx_hi[ai];
                    unsigned ah2 = *(const unsigned*)&sx_hi[ai + 8];
                    unsigned ah1 = *(const unsigned*)&sx_hi[ai + 8 * SLOT];
                    unsigned ah3 = *(const unsigned*)&sx_hi[ai + 8 * SLOT + 8];
                    unsigned al0 = *(const unsigned*)&sx_lo[ai];
                    unsigned al2 = *(const unsigned*)&sx_lo[ai + 8];
                    unsigned al1 = *(const unsigned*)&sx_lo[ai + 8 * SLOT];
                    unsigned al3 = *(const unsigned*)&sx_lo[ai + 8 * SLOT + 8];
#pragma unroll
                    for (int nt = 0; nt < NT; nt++) {
                        mma_bf16(acc[mt][nt], ah0, ah1, ah2, ah3, b0[nt], b1[nt]);
                        mma_bf16(acc[mt][nt], al0, al1, al2, al3, b0[nt], b1[nt]);
                    }
                }
            }
        // no trailing barrier: next iteration's sync protects buffer reuse
    }
    __syncthreads();   // before overlaying smem with the epilogue buffer

    // ---- epilogue: fragments -> smem (overlay) ----
    float* sd = (float*)smem_raw;
#pragma unroll
    for (int mt = 0; mt < 2; mt++) {
        int m0 = wm * 32 + mt * 16 + g;
#pragma unroll
        for (int nt = 0; nt < NT; nt++) {
            int n0 = nt * 8 + 2 * tig;
            *(float2*)&sd[m0 * SD + n0] =
                make_float2(acc[mt][nt][0], acc[mt][nt][1]);
            *(float2*)&sd[(m0 + 8) * SD + n0] =
                make_float2(acc[mt][nt][2], acc[mt][nt][3]);
        }
    }
    __syncthreads();

    // ---- fused maxpool(2x2) + bias + leaky ----
    if (OUTF == 1) {
        // 32 pooled px x 4 chunks = 128 threads; 16 co per thread (NCHO==4)
        int pp = t >> 2, chunk = t & 3;
        int py = pp >> 3, px = pp & 7;
        int ph = ph0 + py, pw = pw0 + px;
        if (ph < POUT && pw < POUT) {
            int mA = (2 * py) * 16 + 2 * px;
            bf16 oh[16], ol[16];
#pragma unroll
            for (int j = 0; j < 16; j++) {
                int co = chunk * 16 + j;
                float v0 = sd[mA * SD + co];
                float v1 = sd[(mA + 1) * SD + co];
                float v2 = sd[(mA + 16) * SD + co];
                float v3 = sd[(mA + 17) * SD + co];
                float m = fmaxf(fmaxf(v0, v1), fmaxf(v2, v3));
                m += __ldg(&bg[co]);
                m = (m >= 0.f) ? m : LEAK * m;
                bf16 hh = __float2bfloat16(m);
                oh[j] = hh;
                ol[j] = __float2bfloat16(m - __bfloat162float(hh));
            }
            size_t gi = ((((size_t)n * NCHO + chunk) * POUT + ph) * POUT + pw) * 16;
            *(uint4*)&outh[gi]     = *(const uint4*)&oh[0];
            *(uint4*)&outh[gi + 8] = *(const uint4*)&oh[8];
            *(uint4*)&outl[gi]     = *(const uint4*)&ol[0];
            *(uint4*)&outl[gi + 8] = *(const uint4*)&ol[8];
        }
    } else {
        // fp32 NCHW output (feeds scalar conv4): 32 px x 4 co-groups of 8
        int pp = t >> 2, cq = t & 3;
        int py = pp >> 3, px = pp & 7;
        int ph = ph0 + py, pw = pw0 + px;
        if (ph < POUT && pw < POUT) {
            int mA = (2 * py) * 16 + 2 * px;
#pragma unroll
            for (int j = 0; j < 8; j++) {
                int co = cq * 8 + j;
                float v0 = sd[mA * SD + co];
                float v1 = sd[(mA + 1) * SD + co];
                float v2 = sd[(mA + 16) * SD + co];
                float v3 = sd[(mA + 17) * SD + co];
                float m = fmaxf(fmaxf(v0, v1), fmaxf(v2, v3));
                m += __ldg(&bg[co]);
                m = (m >= 0.f) ? m : LEAK * m;
                outf[(((size_t)n * CO + co) * POUT + ph) * POUT + pw] = m;
            }
        }
    }
}

// conv2 wrapper: bare launch_bounds(128) — EXACT R10 compile conditions
// (no min-blocks clause; ptxas default heuristic holds ~124 regs, 4 CTA/SM).
__global__ __launch_bounds__(128)
void k_conv2_mma(const bf16* __restrict__ inh, const bf16* __restrict__ inl,
                 const bf16* __restrict__ wf,  const float* __restrict__ bg,
                 bf16* __restrict__ outh, bf16* __restrict__ outl)
{
    conv_mma_body<128, 64, 111, 54, 1, 3>(inh, inl, wf, bg, outh, outl, nullptr);
}

// conv3 wrapper: launch_bounds(128, 6) — verified 80 regs, 6 CTA/SM, 30.8us.
__global__ __launch_bounds__(128, 6)
void k_conv3_mma(const bf16* __restrict__ inh, const bf16* __restrict__ inl,
                 const bf16* __restrict__ wf,  const float* __restrict__ bg,
                 float* __restrict__ outf)
{
    conv_mma_body<64, 32, 54, 26, 0, 2>(inh, inl, wf, bg, nullptr, nullptr, outf);
}

// ---------------------------------------------------------------------------
// Stage 4: conv(32->8, kh=3 kw=2) + bias, no pool.
// ---------------------------------------------------------------------------
__global__ __launch_bounds__(256)
void k_conv4(const float* __restrict__ w4, const float* __restrict__ b4,
             float* __restrict__ out)
{
    __shared__ float sw[8][32][3][2];
    __shared__ float sb[8];
    const int t = threadIdx.x;
    for (int i = t; i < 8 * 32 * 6; i += 256)
        ((float*)sw)[i] = (w4[i] >= 0.f) ? 1.f : -1.f;
    if (t < 8) sb[t] = b4[t];
    __syncthreads();

    int idx = blockIdx.x * 256 + t;
    if (idx >= 32 * 8 * 24 * 25) return;
    int ow = idx % 25; int r = idx / 25;
    int oh = r % 24;   r /= 24;
    int co = r % 8;    int n = r / 8;

    const float* xn = g_buf3 + ((size_t)n * 32) * (26 * 26);
    float a = sb[co];
#pragma unroll 4
    for (int ci = 0; ci < 32; ci++) {
        const float* xr = xn + ci * 676 + oh * 26 + ow;
#pragma unroll
        for (int kh = 0; kh < 3; kh++)
#pragma unroll
            for (int kw = 0; kw < 2; kw++)
                a += sw[co][ci][kh][kw] * __ldg(&xr[kh * 26 + kw]);
    }
    out[idx] = a;
}

// ---------------------------------------------------------------------------
extern "C" void kernel_launch(void* const* d_in, const int* in_sizes, int n_in,
                              void* d_out, int out_size)
{
    (void)in_sizes; (void)n_in; (void)out_size;
    const float* x  = (const float*)d_in[0];
    const float* w1 = (const float*)d_in[1];
    const float* b1 = (const float*)d_in[2];
    const float* w2 = (const float*)d_in[3];
    const float* b2 = (const float*)d_in[4];
    const float* w3 = (const float*)d_in[5];
    const float* b3 = (const float*)d_in[6];
    const float* w4 = (const float*)d_in[7];
    const float* b4 = (const float*)d_in[8];
    float* out = (float*)d_out;

    bf16 *b1h, *b1l, *b2h, *b2l, *w2f, *w3f;
    float* buf3;
    cudaGetSymbolAddress((void**)&b1h, g_b1h);
    cudaGetSymbolAddress((void**)&b1l, g_b1l);
    cudaGetSymbolAddress((void**)&b2h, g_b2h);
    cudaGetSymbolAddress((void**)&b2l, g_b2l);
    cudaGetSymbolAddress((void**)&w2f, g_w2f);
    cudaGetSymbolAddress((void**)&w3f, g_w3f);
    cudaGetSymbolAddress((void**)&buf3, g_buf3);

    // conv2 smem: 3 staging buffers (3*2*4320*2B = 51840) >= epilogue 34816
    const int smem2 = 3 * 2 * (10 * 18 * 24) * 2;  // 51840
    // conv3 smem: 2 staging buffers (2*2*4320*2B = 34560) >= epilogue 18432
    const int smem3 = 2 * 2 * (10 * 18 * 24) * 2;  // 34560
    cudaFuncSetAttribute(k_conv2_mma,
                         cudaFuncAttributeMaxDynamicSharedMemorySize, smem2);

    k_prep<<<dim3(360), 256>>>(w2, w3);

    k_conv1<<<dim3(7, 7, 32), 256>>>(x, w1, b1);

    // conv2: R10 config — 3 buffers, depth-2 prefetch, bare launch_bounds
    k_conv2_mma<<<dim3(14 * 7, 1, 32), 128, smem2>>>(
        b1h, b1l, w2f, b2, b2h, b2l);

    // conv3: R13/R14 config — 2 buffers, min-blocks 6
    k_conv3_mma<<<dim3(7 * 4, 1, 32), 128, smem3>>>(
        b2h, b2l, w3f, b3, buf3);

    k_conv4<<<dim3((32 * 8 * 24 * 25 + 255) / 256), 256>>>(w4, b4, out);
}